// round 17
// baseline (speedup 1.0000x reference)
#include <cuda_runtime.h>

// ContourChamferLoss on GB300 (sm_103a) — round 17
// Fused: scatter -> barrier (scatter-blocks-only arrival) -> 4-thr/query exact
// NN over quadrant 2x2 region (coverage-certified, quad-parallel ring fallback)
// -> deterministic reduction. Query geometry prefetched pre-barrier.

#define NP_TOT 64000
#define NR_TOT 80000
#define NP     8000
#define NR     10000
#define NTOT   (NP + NR)

#define DELTA_P ((float)(NP_TOT - 1) / (float)(NP - 1))
#define DELTA_R ((float)(NR_TOT - 1) / (float)(NR - 1))

#define GK    32
#define NCELL (GK * GK)
#define CS    (1.0f / (float)GK)
#define CAP   128

#define TPB   128
#define QPB   (TPB / 4)
#define NBLK  ((NTOT + QPB - 1) / QPB)        // 563
#define SCATB ((NTOT + TPB - 1) / TPB)        // 141 blocks carry scatter points

#define FULLM 0xFFFFFFFFu

// ---- device scratch (static zero-init; no allocation) ----
// Counters/syncs reset by last block each run -> replay-stable. Bucket slot
// order may vary; min is order-independent; partials keyed by query index.
__device__ int    g_cntP[NCELL];
__device__ int    g_cntR[NCELL];
__device__ float2 g_ptsP[NCELL * CAP];
__device__ float2 g_ptsR[NCELL * CAP];
__device__ float  g_part[NBLK];
__device__ unsigned int g_sync1;
__device__ unsigned int g_sync2;

__device__ __forceinline__ int clamp_cell(int c) {
    return c < 0 ? 0 : (c > GK - 1 ? GK - 1 : c);
}

__device__ __forceinline__ void scan_cell_g(const float2* __restrict__ pts,
                                            const int* __restrict__ cnt,
                                            int c, float px, float py, float& dmin) {
    int m = cnt[c];
    m = m < CAP ? m : CAP;
    const float2* q = pts + c * CAP;
    for (int t = 0; t < m; t++) {
        float2 pp = q[t];
        float ddx = px - pp.x, ddy = py - pp.y;
        dmin = fminf(dmin, fmaf(ddx, ddx, ddy * ddy));
    }
}

__global__ __launch_bounds__(TPB) void chamfer_fused(const float* __restrict__ pc,
                                                     const float* __restrict__ ref,
                                                     float* __restrict__ out) {
    int tid = threadIdx.x;
    int b   = blockIdx.x;

    // ================= phase 1: scatter (blocks 0..SCATB-1 only) =============
    int g = b * TPB + tid;
    if (b < SCATB) {
        if (g < NP) {
            int i = (int)((float)g * DELTA_P);
            float2 p = *reinterpret_cast<const float2*>(pc + 2 * i);
            int c = clamp_cell((int)(p.y * (float)GK)) * GK + clamp_cell((int)(p.x * (float)GK));
            int s = atomicAdd(&g_cntP[c], 1);
            if (s < CAP) g_ptsP[c * CAP + s] = p;
        } else if (g < NTOT) {
            int j = g - NP;
            int i = (int)((float)j * DELTA_R);
            float2 p = *reinterpret_cast<const float2*>(ref + 2 * i);
            int c = clamp_cell((int)(p.y * (float)GK)) * GK + clamp_cell((int)(p.x * (float)GK));
            int s = atomicAdd(&g_cntR[c], 1);
            if (s < CAP) g_ptsR[c * CAP + s] = p;
        }
    }

    // ======= pre-barrier prefetch: query point + cell geometry (input-only) ==
    int q   = g >> 2;
    int par = tid & 3;
    bool active = q < NTOT;

    const float2* pts = g_ptsR;
    const int* cnt = g_cntR;
    float scale = 0.5f / (float)NP;
    float px = 0.f, py = 0.f;
    int cx = 0, cy = 0;

    if (active) {
        const float* own;
        float delta;
        int k;
        if (q < NP) {
            own = pc; delta = DELTA_P; k = q;
        } else {
            pts = g_ptsP; cnt = g_cntP; own = ref;
            delta = DELTA_R; scale = 0.5f / (float)NR; k = q - NP;
        }
        int i = (int)((float)k * delta);
        float2 p = *reinterpret_cast<const float2*>(own + 2 * i);
        px = p.x; py = p.y;
        cx = clamp_cell((int)(px * (float)GK));
        cy = clamp_cell((int)(py * (float)GK));
    }

    // quadrant geometry (registers, input-only)
    float fx = px * (float)GK - (float)cx;
    float fy = py * (float)GK - (float)cy;
    int sx = fx >= 0.5f ? 1 : -1;
    int sy = fy >= 0.5f ? 1 : -1;
    int nxc = cx + sx, nyc = cy + sy;
    bool hx = (nxc >= 0) && (nxc < GK);
    bool hy = (nyc >= 0) && (nyc < GK);
    int tx = (par & 1) ? nxc : cx;
    int ty = (par >> 1) ? nyc : cy;
    bool valid = active && ((par & 1) ? hx : true) && ((par >> 1) ? hy : true);

    // coverage radius to nearest interior region edge (domain edges: infinite)
    float cov = 1e30f;
    {
        int xloC = (hx && sx < 0) ? nxc : cx;
        int xhiC = (hx && sx > 0) ? nxc : cx;
        int yloC = (hy && sy < 0) ? nyc : cy;
        int yhiC = (hy && sy > 0) ? nyc : cy;
        if (xloC > 0)      cov = fminf(cov, px - (float)xloC * CS);
        if (xhiC < GK - 1) cov = fminf(cov, (float)(xhiC + 1) * CS - px);
        if (yloC > 0)      cov = fminf(cov, py - (float)yloC * CS);
        if (yhiC < GK - 1) cov = fminf(cov, (float)(yhiC + 1) * CS - py);
    }

    // ================= barrier: wait for the 141 scatter blocks ==============
    __syncthreads();
    if (tid == 0) {
        unsigned int v;
        if (b < SCATB) {
            __threadfence();                      // release scatter writes
            atomicAdd(&g_sync1, 1u);
        }
        do {
            asm volatile("ld.acquire.gpu.u32 %0, [%1];"
                         : "=r"(v) : "l"(&g_sync1) : "memory");
            if (v < SCATB) __nanosleep(64);
        } while (v < SCATB);
    }
    __syncthreads();

    // ================= phase 2: search (bucket reads only) ===================
    float v = 0.f;
    unsigned int qmask = 0xFu << ((tid & 31) & ~3);   // this quad's 4 lanes

    if (active) {
        int m = 0, base = 0;
        if (valid) {
            int cell = ty * GK + tx;
            base = cell * CAP;
            m = cnt[cell];
            m = m < CAP ? m : CAP;
        }

        float dmin = 1e30f;
        {
            const float2* basep = pts + base;             // 16B-aligned
            int s = 0;
            for (; s + 2 <= m; s += 2) {                  // 2 points per LDG.128
                float4 pq = *reinterpret_cast<const float4*>(basep + s);
                float dx0 = px - pq.x, dy0 = py - pq.y;
                float dx1 = px - pq.z, dy1 = py - pq.w;
                dmin = fminf(dmin, fmaf(dx0, dx0, dy0 * dy0));
                dmin = fminf(dmin, fmaf(dx1, dx1, dy1 * dy1));
            }
            if (s < m) {
                float2 pp = basep[s];
                float ddx = px - pp.x, ddy = py - pp.y;
                dmin = fminf(dmin, fmaf(ddx, ddx, ddy * ddy));
            }
        }

        // combine quad (uniform dmin across the 4 lanes afterwards)
        dmin = fminf(dmin, __shfl_xor_sync(qmask, dmin, 1));
        dmin = fminf(dmin, __shfl_xor_sync(qmask, dmin, 2));

        // certified? else quad-parallel expanding-square fallback (rare).
        if (dmin > cov * cov) {
            int r = 0;
            float covr = 0.f;
            while (dmin > covr * covr && r < GK - 1) {
                r++;
                covr = (float)r * CS;
                int idx = 0;
                if (r == 1) {
                    for (int yy = cy - 1; yy <= cy + 1; yy++) {
                        if (yy < 0 || yy >= GK) continue;
                        for (int xx = cx - 1; xx <= cx + 1; xx++) {
                            if (xx < 0 || xx >= GK) continue;
                            if ((idx++ & 3) == par)
                                scan_cell_g(pts, cnt, yy * GK + xx, px, py, dmin);
                        }
                    }
                } else {
                    for (int dy = -r; dy <= r; dy++) {
                        int yy = cy + dy;
                        if (yy < 0 || yy >= GK) continue;
                        int step = (dy == -r || dy == r) ? 1 : 2 * r;
                        for (int xx = cx - r; xx <= cx + r; xx += step) {
                            if (xx < 0 || xx >= GK) continue;
                            if ((idx++ & 3) == par)
                                scan_cell_g(pts, cnt, yy * GK + xx, px, py, dmin);
                        }
                    }
                }
                dmin = fminf(dmin, __shfl_xor_sync(qmask, dmin, 1));
                dmin = fminf(dmin, __shfl_xor_sync(qmask, dmin, 2));
            }
        }

        if (par == 0) v = sqrtf(dmin) * scale;
    }

    // ================= phase 3: deterministic reduction ======================
    #pragma unroll
    for (int o = 16; o > 0; o >>= 1)
        v += __shfl_xor_sync(FULLM, v, o);

    __shared__ float sw[TPB / 32];
    int lane = tid & 31, wid = tid >> 5;
    if (lane == 0) sw[wid] = v;
    __syncthreads();

    __shared__ int lastf;
    if (tid == 0) {
        float s = 0.f;
        #pragma unroll
        for (int w = 0; w < TPB / 32; w++) s += sw[w];
        g_part[b] = s;
        __threadfence();
        unsigned int done = atomicAdd(&g_sync2, 1u);
        lastf = (done == NBLK - 1) ? 1 : 0;
    }
    __syncthreads();

    if (lastf) {
        if (tid == 0) __threadfence();
        __syncthreads();

        float acc = 0.f;
        for (int t = tid; t < NBLK; t += TPB)    // fixed order -> deterministic
            acc += g_part[t];

        #pragma unroll
        for (int o = 16; o > 0; o >>= 1)
            acc += __shfl_xor_sync(FULLM, acc, o);
        if (lane == 0) sw[wid] = acc;
        __syncthreads();

        if (tid == 0) {
            float t = 0.f;
            #pragma unroll
            for (int w = 0; w < TPB / 32; w++) t += sw[w];
            out[0] = t;
            g_sync1 = 0;
            g_sync2 = 0;
        }
        for (int c = tid; c < NCELL; c += TPB) {
            g_cntP[c] = 0;
            g_cntR[c] = 0;
        }
    }
}

extern "C" void kernel_launch(void* const* d_in, const int* in_sizes, int n_in,
                              void* d_out, int out_size) {
    const float* pc  = (const float*)d_in[0];   // img_render_points (64000 x 2)
    const float* ref = (const float*)d_in[1];   // ref point cloud   (80000 x 2)

    chamfer_fused<<<NBLK, TPB>>>(pc, ref, (float*)d_out);
}